// round 1
// baseline (speedup 1.0000x reference)
#include <cuda_runtime.h>
#include <cuda_bf16.h>

// Problem constants (fixed by the dataset)
#define BB   4
#define HH   8
#define NN   256
#define DVD  64
#define NKD  64
#define EKD  16
#define QD   80      // NK_DIM + EK_DIM
#define TQ   16      // queries per block

// grid = 32 (b*h) * 16 (q tiles) = 512 blocks, 256 threads each.
__global__ __launch_bounds__(256, 2)
void sdpea_kernel(const float* __restrict__ qg,
                  const float* __restrict__ nk,
                  const float* __restrict__ ek,
                  const float* __restrict__ v,
                  const int*   __restrict__ mask,
                  float* __restrict__ out,       // [B,H,N,DV]
                  float* __restrict__ attn_out)  // [B,H,N,N]
{
    __shared__ float qsm[TQ][QD];   // q tile (qn||qe)
    __shared__ float Ssm[TQ][NN];   // scores -> probs

    const int bx = blockIdx.x;
    const int bh = bx >> 4;          // 0..31  (b*H + h)
    const int qt = bx & 15;          // 0..15
    const int b  = bh >> 3;
    const int q0 = qt * TQ;
    const int t  = threadIdx.x;      // 0..255

    // ---- load q tile (16 x 80 floats) ----
    for (int i = t; i < TQ * QD; i += 256) {
        int qq = i / QD, d = i % QD;
        qsm[qq][d] = qg[(size_t)((bh * NN) + q0 + qq) * QD + d];
    }
    __syncthreads();

    // ---- phase 1: scores; one key per thread ----
    {
        const int k = t;
        const float4* nkrow = (const float4*)(nk + (size_t)(bh * NN + k) * NKD);
        float4 nkr[16];
        #pragma unroll
        for (int i = 0; i < 16; i++) nkr[i] = nkrow[i];

        const int* mrow = mask + (size_t)b * NN * NN;

        #pragma unroll 4
        for (int qq = 0; qq < TQ; qq++) {
            const int qa = q0 + qq;
            float s = 0.f;
            #pragma unroll
            for (int i = 0; i < 16; i++) {
                float4 nv = nkr[i];
                s += nv.x * qsm[qq][4*i+0] + nv.y * qsm[qq][4*i+1]
                   + nv.z * qsm[qq][4*i+2] + nv.w * qsm[qq][4*i+3];
            }
            const float4* ekr =
                (const float4*)(ek + ((size_t)(bh * NN + qa) * NN + k) * EKD);
            #pragma unroll
            for (int i = 0; i < 4; i++) {
                float4 ev = ekr[i];
                s += ev.x * qsm[qq][NKD+4*i+0] + ev.y * qsm[qq][NKD+4*i+1]
                   + ev.z * qsm[qq][NKD+4*i+2] + ev.w * qsm[qq][NKD+4*i+3];
            }
            s *= 0.125f;                         // / TEMPERATURE
            if (mrow[qa * NN + k] == 0) s = -1e9f;
            Ssm[qq][k] = s;
        }
    }
    __syncthreads();

    // ---- phase 2: softmax, one warp per row (8 warps, 16 rows) ----
    {
        const int w = t >> 5, lane = t & 31;
        for (int qq = w; qq < TQ; qq += 8) {
            float vals[8];
            float mx = -3.4e38f;
            #pragma unroll
            for (int i = 0; i < 8; i++) {
                vals[i] = Ssm[qq][lane + 32*i];
                mx = fmaxf(mx, vals[i]);
            }
            #pragma unroll
            for (int o = 16; o > 0; o >>= 1)
                mx = fmaxf(mx, __shfl_xor_sync(0xffffffffu, mx, o));
            float sum = 0.f;
            #pragma unroll
            for (int i = 0; i < 8; i++) {
                vals[i] = __expf(vals[i] - mx);
                sum += vals[i];
            }
            #pragma unroll
            for (int o = 16; o > 0; o >>= 1)
                sum += __shfl_xor_sync(0xffffffffu, sum, o);
            const float inv = 1.f / sum;
            float* arow = attn_out + (size_t)((bh * NN) + q0 + qq) * NN;
            #pragma unroll
            for (int i = 0; i < 8; i++) {
                float p = vals[i] * inv;
                Ssm[qq][lane + 32*i] = p;
                arow[lane + 32*i]   = p;
            }
        }
    }
    __syncthreads();

    // ---- phase 3: output = P @ V ; thread owns (d, 4 q-rows) ----
    {
        const int d = t & 63, g = t >> 6;       // g in 0..3
        float acc0 = 0.f, acc1 = 0.f, acc2 = 0.f, acc3 = 0.f;
        const float* vb = v + (size_t)bh * NN * DVD + d;
        #pragma unroll 4
        for (int k = 0; k < NN; k++) {
            float vv = vb[(size_t)k * DVD];
            acc0 += Ssm[g     ][k] * vv;
            acc1 += Ssm[g +  4][k] * vv;
            acc2 += Ssm[g +  8][k] * vv;
            acc3 += Ssm[g + 12][k] * vv;
        }
        float* ob = out + (size_t)((bh * NN) + q0) * DVD + d;
        ob[(size_t)(g     ) * DVD] = acc0;
        ob[(size_t)(g +  4) * DVD] = acc1;
        ob[(size_t)(g +  8) * DVD] = acc2;
        ob[(size_t)(g + 12) * DVD] = acc3;
    }
}

extern "C" void kernel_launch(void* const* d_in, const int* in_sizes, int n_in,
                              void* d_out, int out_size)
{
    const float* q    = (const float*)d_in[0];
    const float* nk   = (const float*)d_in[1];
    const float* ek   = (const float*)d_in[2];
    const float* v    = (const float*)d_in[3];
    const int*   mask = (const int*)d_in[4];

    float* out      = (float*)d_out;                       // [4,8,256,64]
    float* attn_out = out + (size_t)BB * HH * NN * DVD;    // [4,8,256,256]

    dim3 grid(BB * HH * (NN / TQ));   // 512
    dim3 block(256);
    sdpea_kernel<<<grid, block>>>(q, nk, ek, v, mask, out, attn_out);
}

// round 2
// speedup vs baseline: 1.0847x; 1.0847x over previous
#include <cuda_runtime.h>
#include <cuda_bf16.h>

// Problem constants (fixed by the dataset)
#define BB   4
#define HH   8
#define NN   256
#define DVD  64
#define NKD  64
#define EKD  16
#define QD   80      // NK_DIM + EK_DIM
#define TQ   16      // queries per block

// grid = 32 (b*h) * 16 (q tiles) = 512 blocks, 256 threads each, 4 CTAs/SM.
__global__ __launch_bounds__(256, 4)
void sdpea_kernel(const float* __restrict__ qg,
                  const float* __restrict__ nk,
                  const float* __restrict__ ek,
                  const float* __restrict__ v,
                  const int*   __restrict__ mask,
                  float* __restrict__ out,       // [B,H,N,DV]
                  float* __restrict__ attn_out)  // [B,H,N,N]
{
    __shared__ float qsm[TQ][QD];   // q tile (qn||qe), rows 320B (16B aligned)
    __shared__ float Ssm[TQ][NN];   // scores -> probs

    const int bx = blockIdx.x;
    const int bh = bx >> 4;          // 0..31  (b*H + h)
    const int qt = bx & 15;          // 0..15
    const int b  = bh >> 3;
    const int q0 = qt * TQ;
    const int t  = threadIdx.x;      // 0..255

    // ---- load q tile (16 x 80 floats) ----
    for (int i = t; i < TQ * QD; i += 256) {
        int qq = i / QD, d = i % QD;
        qsm[qq][d] = qg[(size_t)((bh * NN) + q0 + qq) * QD + d];
    }
    __syncthreads();

    // ---- phase 1: scores; one key per thread, 2 halves of 8 queries ----
    {
        const int k = t;
        const float4* nkrow = (const float4*)(nk + (size_t)(bh * NN + k) * NKD);
        const int*    mrow  = mask + (size_t)b * NN * NN + k;

        #pragma unroll
        for (int half = 0; half < 2; half++) {
            const int qbase = half * 8;
            float s[8];
            #pragma unroll
            for (int j = 0; j < 8; j++) s[j] = 0.f;

            // node part: stream nk row (L1-hit on second half)
            #pragma unroll
            for (int i = 0; i < 16; i++) {
                const float4 nv = nkrow[i];
                #pragma unroll
                for (int j = 0; j < 8; j++) {
                    const float4 qv = *(const float4*)&qsm[qbase + j][4 * i];
                    s[j] += nv.x * qv.x + nv.y * qv.y + nv.z * qv.z + nv.w * qv.w;
                }
            }

            // edge part: 4 x float4 per query, streamed once from DRAM
            #pragma unroll
            for (int j = 0; j < 8; j++) {
                const int qa = q0 + qbase + j;
                const float4* ekr =
                    (const float4*)(ek + ((size_t)(bh * NN + qa) * NN + k) * EKD);
                const float4 e0 = ekr[0], e1 = ekr[1], e2 = ekr[2], e3 = ekr[3];
                const float4 a0 = *(const float4*)&qsm[qbase + j][NKD +  0];
                const float4 a1 = *(const float4*)&qsm[qbase + j][NKD +  4];
                const float4 a2 = *(const float4*)&qsm[qbase + j][NKD +  8];
                const float4 a3 = *(const float4*)&qsm[qbase + j][NKD + 12];
                s[j] += e0.x * a0.x + e0.y * a0.y + e0.z * a0.z + e0.w * a0.w
                      + e1.x * a1.x + e1.y * a1.y + e1.z * a1.z + e1.w * a1.w
                      + e2.x * a2.x + e2.y * a2.y + e2.z * a2.z + e2.w * a2.w
                      + e3.x * a3.x + e3.y * a3.y + e3.z * a3.z + e3.w * a3.w;
            }

            // mask + store
            #pragma unroll
            for (int j = 0; j < 8; j++) {
                const int qa = q0 + qbase + j;
                float sv = s[j] * 0.125f;              // / TEMPERATURE
                if (mrow[qa * NN] == 0) sv = -1000000000.0f;
                Ssm[qbase + j][k] = sv;
            }
        }
    }
    __syncthreads();

    // ---- phase 2: softmax, one warp per row (8 warps, 16 rows) ----
    {
        const int w = t >> 5, lane = t & 31;
        for (int qq = w; qq < TQ; qq += 8) {
            float vals[8];
            float mx = -3.4e38f;
            #pragma unroll
            for (int i = 0; i < 8; i++) {
                vals[i] = Ssm[qq][lane + 32 * i];
                mx = fmaxf(mx, vals[i]);
            }
            #pragma unroll
            for (int o = 16; o > 0; o >>= 1)
                mx = fmaxf(mx, __shfl_xor_sync(0xffffffffu, mx, o));
            float sum = 0.f;
            #pragma unroll
            for (int i = 0; i < 8; i++) {
                vals[i] = __expf(vals[i] - mx);
                sum += vals[i];
            }
            #pragma unroll
            for (int o = 16; o > 0; o >>= 1)
                sum += __shfl_xor_sync(0xffffffffu, sum, o);
            const float inv = 1.f / sum;
            float* arow = attn_out + (size_t)((bh * NN) + q0 + qq) * NN;
            #pragma unroll
            for (int i = 0; i < 8; i++) {
                float p = vals[i] * inv;
                Ssm[qq][lane + 32 * i] = p;
                arow[lane + 32 * i]    = p;
            }
        }
    }
    __syncthreads();

    // ---- phase 3: output = P @ V ; thread owns (d, 4 q-rows) ----
    {
        const int d = t & 63, g = t >> 6;       // g in 0..3
        float acc0 = 0.f, acc1 = 0.f, acc2 = 0.f, acc3 = 0.f;
        const float* vb = v + (size_t)bh * NN * DVD + d;
        #pragma unroll 4
        for (int k = 0; k < NN; k++) {
            float vv = vb[(size_t)k * DVD];
            acc0 += Ssm[g     ][k] * vv;
            acc1 += Ssm[g +  4][k] * vv;
            acc2 += Ssm[g +  8][k] * vv;
            acc3 += Ssm[g + 12][k] * vv;
        }
        float* ob = out + (size_t)((bh * NN) + q0) * DVD + d;
        ob[(size_t)(g     ) * DVD] = acc0;
        ob[(size_t)(g +  4) * DVD] = acc1;
        ob[(size_t)(g +  8) * DVD] = acc2;
        ob[(size_t)(g + 12) * DVD] = acc3;
    }
}

extern "C" void kernel_launch(void* const* d_in, const int* in_sizes, int n_in,
                              void* d_out, int out_size)
{
    const float* q    = (const float*)d_in[0];
    const float* nk   = (const float*)d_in[1];
    const float* ek   = (const float*)d_in[2];
    const float* v    = (const float*)d_in[3];
    const int*   mask = (const int*)d_in[4];

    float* out      = (float*)d_out;                       // [4,8,256,64]
    float* attn_out = out + (size_t)BB * HH * NN * DVD;    // [4,8,256,256]

    dim3 grid(BB * HH * (NN / TQ));   // 512
    dim3 block(256);
    sdpea_kernel<<<grid, block>>>(q, nk, ek, v, mask, out, attn_out);
}

// round 5
// speedup vs baseline: 1.1850x; 1.0925x over previous
#include <cuda_runtime.h>
#include <cuda_bf16.h>

// Problem constants (fixed by the dataset)
#define BB   4
#define HH   8
#define NN   256
#define DVD  64
#define NKD  64
#define EKD  16
#define QD   80      // NK_DIM + EK_DIM
#define TQ   16      // queries per block

// ============================================================
// Kernel A: E[bh,q,k] = qe[bh,q,:] . ek[bh,q,k,:]
// Pure DRAM stream of ek (134 MB). One block per (bh,q) row,
// one thread per key. Written into the attn region of d_out
// (scratch; kernel B reads it then overwrites with probs).
// ============================================================
__global__ __launch_bounds__(256, 8)
void edge_kernel(const float* __restrict__ qg,
                 const float* __restrict__ ek,
                 float* __restrict__ E)
{
    const int bx   = blockIdx.x;        // bh*256 + q
    const int bh   = bx >> 8;
    const int qrow = bx & 255;
    const int k    = threadIdx.x;

    // qe (16 floats) — uniform across the block, broadcast via L1
    const float4* qp = (const float4*)(qg + ((size_t)(bh * NN) + qrow) * QD + NKD);
    const float4 a0 = qp[0], a1 = qp[1], a2 = qp[2], a3 = qp[3];

    const float4* ekr =
        (const float4*)(ek + ((size_t)(bh * NN + qrow) * NN + k) * EKD);
    const float4 e0 = ekr[0], e1 = ekr[1], e2 = ekr[2], e3 = ekr[3];

    float s = e0.x * a0.x + e0.y * a0.y + e0.z * a0.z + e0.w * a0.w
            + e1.x * a1.x + e1.y * a1.y + e1.z * a1.z + e1.w * a1.w
            + e2.x * a2.x + e2.y * a2.y + e2.z * a2.z + e2.w * a2.w
            + e3.x * a3.x + e3.y * a3.y + e3.z * a3.z + e3.w * a3.w;

    E[(size_t)(bh * NN + qrow) * NN + k] = s;
}

// ============================================================
// Kernel B: node part + E + mask -> softmax -> attn + P@V
// grid = 32 (b*h) * 16 (q tiles) = 512 blocks, 256 threads.
// ============================================================
__global__ __launch_bounds__(256, 4)
void sdpea_kernel(const float* __restrict__ qg,
                  const float* __restrict__ nk,
                  const float* __restrict__ v,
                  const int*   __restrict__ mask,
                  const float* __restrict__ E,   // == attn_out (scratch)
                  float* __restrict__ out,       // [B,H,N,DV]
                  float* __restrict__ attn_out)  // [B,H,N,N]
{
    __shared__ float qsm[TQ][QD];   // q tile (qn||qe), rows 320B (16B aligned)
    __shared__ float Ssm[TQ][NN];   // scores -> probs

    const int bx = blockIdx.x;
    const int bh = bx >> 4;          // 0..31  (b*H + h)
    const int qt = bx & 15;          // 0..15
    const int b  = bh >> 3;
    const int q0 = qt * TQ;
    const int t  = threadIdx.x;      // 0..255

    // ---- load q tile (16 x 80 floats) ----
    for (int i = t; i < TQ * QD; i += 256) {
        int qq = i / QD, d = i % QD;
        qsm[qq][d] = qg[(size_t)((bh * NN) + q0 + qq) * QD + d];
    }
    __syncthreads();

    // ---- phase 1: scores; one key per thread, 2 halves of 8 queries ----
    {
        const int k = t;
        const float4* nkrow = (const float4*)(nk + (size_t)(bh * NN + k) * NKD);
        const int*    mrow  = mask + (size_t)b * NN * NN + k;
        const float*  Erow  = E + (size_t)bh * NN * NN + k;

        #pragma unroll
        for (int half = 0; half < 2; half++) {
            const int qbase = half * 8;

            // start the 8 independent E loads + 8 mask loads early (MLP)
            float s[8];
            int   m[8];
            #pragma unroll
            for (int j = 0; j < 8; j++) {
                const int qa = q0 + qbase + j;
                s[j] = Erow[(size_t)qa * NN];
                m[j] = mrow[qa * NN];
            }

            // node part: stream nk row (L1-hit on second half)
            #pragma unroll
            for (int i = 0; i < 16; i++) {
                const float4 nv = nkrow[i];
                #pragma unroll
                for (int j = 0; j < 8; j++) {
                    const float4 qv = *(const float4*)&qsm[qbase + j][4 * i];
                    s[j] += nv.x * qv.x + nv.y * qv.y + nv.z * qv.z + nv.w * qv.w;
                }
            }

            // scale + mask + store
            #pragma unroll
            for (int j = 0; j < 8; j++) {
                float sv = s[j] * 0.125f;              // / TEMPERATURE
                if (m[j] == 0) sv = -1000000000.0f;
                Ssm[qbase + j][k] = sv;
            }
        }
    }
    __syncthreads();

    // ---- phase 2: softmax, one warp per row (8 warps, 16 rows) ----
    {
        const int w = t >> 5, lane = t & 31;
        for (int qq = w; qq < TQ; qq += 8) {
            float vals[8];
            float mx = -3.4e38f;
            #pragma unroll
            for (int i = 0; i < 8; i++) {
                vals[i] = Ssm[qq][lane + 32 * i];
                mx = fmaxf(mx, vals[i]);
            }
            #pragma unroll
            for (int o = 16; o > 0; o >>= 1)
                mx = fmaxf(mx, __shfl_xor_sync(0xffffffffu, mx, o));
            float sum = 0.f;
            #pragma unroll
            for (int i = 0; i < 8; i++) {
                vals[i] = __expf(vals[i] - mx);
                sum += vals[i];
            }
            #pragma unroll
            for (int o = 16; o > 0; o >>= 1)
                sum += __shfl_xor_sync(0xffffffffu, sum, o);
            const float inv = 1.f / sum;
            float* arow = attn_out + (size_t)((bh * NN) + q0 + qq) * NN;
            #pragma unroll
            for (int i = 0; i < 8; i++) {
                float p = vals[i] * inv;
                Ssm[qq][lane + 32 * i] = p;
                arow[lane + 32 * i]    = p;
            }
        }
    }
    __syncthreads();

    // ---- phase 3: output = P @ V ; thread owns (d, 4 q-rows) ----
    {
        const int d = t & 63, g = t >> 6;       // g in 0..3
        float acc0 = 0.f, acc1 = 0.f, acc2 = 0.f, acc3 = 0.f;
        const float* vb = v + (size_t)bh * NN * DVD + d;
        #pragma unroll 4
        for (int k = 0; k < NN; k++) {
            float vv = vb[(size_t)k * DVD];
            acc0 += Ssm[g     ][k] * vv;
            acc1 += Ssm[g +  4][k] * vv;
            acc2 += Ssm[g +  8][k] * vv;
            acc3 += Ssm[g + 12][k] * vv;
        }
        float* ob = out + (size_t)((bh * NN) + q0) * DVD + d;
        ob[(size_t)(g     ) * DVD] = acc0;
        ob[(size_t)(g +  4) * DVD] = acc1;
        ob[(size_t)(g +  8) * DVD] = acc2;
        ob[(size_t)(g + 12) * DVD] = acc3;
    }
}

extern "C" void kernel_launch(void* const* d_in, const int* in_sizes, int n_in,
                              void* d_out, int out_size)
{
    const float* q    = (const float*)d_in[0];
    const float* nk   = (const float*)d_in[1];
    const float* ek   = (const float*)d_in[2];
    const float* v    = (const float*)d_in[3];
    const int*   mask = (const int*)d_in[4];

    float* out      = (float*)d_out;                       // [4,8,256,64]
    float* attn_out = out + (size_t)BB * HH * NN * DVD;    // [4,8,256,256]

    // Kernel A: edge scores into attn region (scratch)
    edge_kernel<<<BB * HH * NN, 256>>>(q, ek, attn_out);

    // Kernel B: node + E -> softmax -> attn + output
    sdpea_kernel<<<BB * HH * (NN / TQ), 256>>>(q, nk, v, mask,
                                               attn_out, out, attn_out);
}

// round 6
// speedup vs baseline: 1.3395x; 1.1303x over previous
#include <cuda_runtime.h>
#include <cuda_bf16.h>

// Problem constants (fixed by the dataset)
#define BB   4
#define HH   8
#define NN   256
#define DVD  64
#define NKD  64
#define EKD  16
#define QD   80      // NK_DIM + EK_DIM
#define TQ   16      // queries per block
#define KC   64      // nk keys per smem chunk
#define NKPAD 68     // padded row stride (floats) for conflict-free LDS

// ============================================================
// Kernel A: E[bh,q,k] = qe[bh,q,:] . ek[bh,q,k,:]
// Pure DRAM stream of ek (134 MB). One block per (bh,q) row,
// one thread per key. Written into the attn region of d_out
// (scratch; kernel B reads it then overwrites with probs).
// ============================================================
__global__ __launch_bounds__(256, 8)
void edge_kernel(const float* __restrict__ qg,
                 const float* __restrict__ ek,
                 float* __restrict__ E)
{
    const int bx   = blockIdx.x;        // bh*256 + q
    const int bh   = bx >> 8;
    const int qrow = bx & 255;
    const int k    = threadIdx.x;

    // qe (16 floats) — uniform across the block, broadcast via L1
    const float4* qp = (const float4*)(qg + ((size_t)(bh * NN) + qrow) * QD + NKD);
    const float4 a0 = qp[0], a1 = qp[1], a2 = qp[2], a3 = qp[3];

    const float4* ekr =
        (const float4*)(ek + ((size_t)(bh * NN + qrow) * NN + k) * EKD);
    const float4 e0 = ekr[0], e1 = ekr[1], e2 = ekr[2], e3 = ekr[3];

    float s = e0.x * a0.x + e0.y * a0.y + e0.z * a0.z + e0.w * a0.w
            + e1.x * a1.x + e1.y * a1.y + e1.z * a1.z + e1.w * a1.w
            + e2.x * a2.x + e2.y * a2.y + e2.z * a2.z + e2.w * a2.w
            + e3.x * a3.x + e3.y * a3.y + e3.z * a3.z + e3.w * a3.w;

    E[(size_t)(bh * NN + qrow) * NN + k] = s;
}

// ============================================================
// Kernel B: node part + E + mask -> softmax -> attn + P@V
// grid = 32 (b*h) * 16 (q tiles) = 512 blocks, 256 threads.
// nk staged through smem in 4 coalesced, conflict-free chunks.
// ============================================================
__global__ __launch_bounds__(256, 4)
void sdpea_kernel(const float* __restrict__ qg,
                  const float* __restrict__ nk,
                  const float* __restrict__ v,
                  const int*   __restrict__ mask,
                  const float* __restrict__ E,   // == attn_out (scratch)
                  float* __restrict__ out,       // [B,H,N,DV]
                  float* __restrict__ attn_out)  // [B,H,N,N]
{
    __shared__ float qsm[TQ][QD];      // q tile (qn||qe)
    __shared__ float Ssm[TQ][NN];      // scores -> probs
    __shared__ float nks[KC][NKPAD];   // nk chunk, padded

    const int bx = blockIdx.x;
    const int bh = bx >> 4;          // 0..31  (b*H + h)
    const int qt = bx & 15;          // 0..15
    const int b  = bh >> 3;
    const int q0 = qt * TQ;
    const int t  = threadIdx.x;      // 0..255

    // ---- load q tile (16 x 80 floats) ----
    for (int i = t; i < TQ * QD; i += 256) {
        int qq = i / QD, d = i % QD;
        qsm[qq][d] = qg[(size_t)((bh * NN) + q0 + qq) * QD + d];
    }

    // ---- phase 1: scores in 4 key-chunks of 64 ----
    // thread = (k_local = t&63, q_group g = t>>6); queries {g, g+4, g+8, g+12}
    const int kl = t & 63;
    const int g  = t >> 6;
    const float* Ebh  = E + (size_t)bh * NN * NN;
    const int*   mb   = mask + (size_t)b * NN * NN;

    for (int c = 0; c < 4; c++) {
        const int kbase = c * KC;
        __syncthreads();   // protect nks from previous chunk's readers

        // coalesced stage: 64 rows x 64 floats, 4 float4 per thread
        {
            const float4* src = (const float4*)(nk + (size_t)(bh * NN + kbase) * NKD);
            #pragma unroll
            for (int it = 0; it < 4; it++) {
                const int idx  = t + it * 256;       // 0..1023
                const int row  = idx >> 4;           // /16
                const int col4 = idx & 15;
                const float4 vv = src[(size_t)row * 16 + col4];
                *(float4*)&nks[row][col4 * 4] = vv;
            }
        }
        __syncthreads();

        const int k = kbase + kl;

        // prefetch E + mask for this thread's 4 (q,k) pairs
        float ev[4]; int m[4];
        #pragma unroll
        for (int j = 0; j < 4; j++) {
            const int qa = q0 + g + 4 * j;
            ev[j] = Ebh[(size_t)qa * NN + k];
            m[j]  = mb[qa * NN + k];
        }

        float acc0 = 0.f, acc1 = 0.f, acc2 = 0.f, acc3 = 0.f;
        #pragma unroll
        for (int i = 0; i < 16; i++) {
            const float4 nv = *(const float4*)&nks[kl][4 * i];
            const float4 q0v = *(const float4*)&qsm[g     ][4 * i];
            const float4 q1v = *(const float4*)&qsm[g +  4][4 * i];
            const float4 q2v = *(const float4*)&qsm[g +  8][4 * i];
            const float4 q3v = *(const float4*)&qsm[g + 12][4 * i];
            acc0 += nv.x * q0v.x + nv.y * q0v.y + nv.z * q0v.z + nv.w * q0v.w;
            acc1 += nv.x * q1v.x + nv.y * q1v.y + nv.z * q1v.z + nv.w * q1v.w;
            acc2 += nv.x * q2v.x + nv.y * q2v.y + nv.z * q2v.z + nv.w * q2v.w;
            acc3 += nv.x * q3v.x + nv.y * q3v.y + nv.z * q3v.z + nv.w * q3v.w;
        }

        float sv;
        sv = (acc0 + ev[0]) * 0.125f; if (m[0] == 0) sv = -1000000000.0f; Ssm[g     ][k] = sv;
        sv = (acc1 + ev[1]) * 0.125f; if (m[1] == 0) sv = -1000000000.0f; Ssm[g +  4][k] = sv;
        sv = (acc2 + ev[2]) * 0.125f; if (m[2] == 0) sv = -1000000000.0f; Ssm[g +  8][k] = sv;
        sv = (acc3 + ev[3]) * 0.125f; if (m[3] == 0) sv = -1000000000.0f; Ssm[g + 12][k] = sv;
    }
    __syncthreads();

    // ---- phase 2: softmax, one warp per row (8 warps, 16 rows) ----
    {
        const int w = t >> 5, lane = t & 31;
        for (int qq = w; qq < TQ; qq += 8) {
            float vals[8];
            float mx = -3.4e38f;
            #pragma unroll
            for (int i = 0; i < 8; i++) {
                vals[i] = Ssm[qq][lane + 32 * i];
                mx = fmaxf(mx, vals[i]);
            }
            #pragma unroll
            for (int o = 16; o > 0; o >>= 1)
                mx = fmaxf(mx, __shfl_xor_sync(0xffffffffu, mx, o));
            float sum = 0.f;
            #pragma unroll
            for (int i = 0; i < 8; i++) {
                vals[i] = __expf(vals[i] - mx);
                sum += vals[i];
            }
            #pragma unroll
            for (int o = 16; o > 0; o >>= 1)
                sum += __shfl_xor_sync(0xffffffffu, sum, o);
            const float inv = 1.f / sum;
            float* arow = attn_out + (size_t)((bh * NN) + q0 + qq) * NN;
            #pragma unroll
            for (int i = 0; i < 8; i++) {
                float p = vals[i] * inv;
                Ssm[qq][lane + 32 * i] = p;
                arow[lane + 32 * i]    = p;
            }
        }
    }
    __syncthreads();

    // ---- phase 3: output = P @ V ; thread owns (d, 4 q-rows) ----
    {
        const int d = t & 63, gg = t >> 6;      // gg in 0..3
        float acc0 = 0.f, acc1 = 0.f, acc2 = 0.f, acc3 = 0.f;
        const float* vb = v + (size_t)bh * NN * DVD + d;
        #pragma unroll 4
        for (int k = 0; k < NN; k++) {
            float vv = vb[(size_t)k * DVD];
            acc0 += Ssm[gg     ][k] * vv;
            acc1 += Ssm[gg +  4][k] * vv;
            acc2 += Ssm[gg +  8][k] * vv;
            acc3 += Ssm[gg + 12][k] * vv;
        }
        float* ob = out + (size_t)((bh * NN) + q0) * DVD + d;
        ob[(size_t)(gg     ) * DVD] = acc0;
        ob[(size_t)(gg +  4) * DVD] = acc1;
        ob[(size_t)(gg +  8) * DVD] = acc2;
        ob[(size_t)(gg + 12) * DVD] = acc3;
    }
}

extern "C" void kernel_launch(void* const* d_in, const int* in_sizes, int n_in,
                              void* d_out, int out_size)
{
    const float* q    = (const float*)d_in[0];
    const float* nk   = (const float*)d_in[1];
    const float* ek   = (const float*)d_in[2];
    const float* v    = (const float*)d_in[3];
    const int*   mask = (const int*)d_in[4];

    float* out      = (float*)d_out;                       // [4,8,256,64]
    float* attn_out = out + (size_t)BB * HH * NN * DVD;    // [4,8,256,256]

    // Kernel A: edge scores into attn region (scratch)
    edge_kernel<<<BB * HH * NN, 256>>>(q, ek, attn_out);

    // Kernel B: node + E -> softmax -> attn + output
    sdpea_kernel<<<BB * HH * (NN / TQ), 256>>>(q, nk, v, mask,
                                               attn_out, out, attn_out);
}

// round 7
// speedup vs baseline: 1.5887x; 1.1860x over previous
#include <cuda_runtime.h>
#include <cuda_bf16.h>

// Problem constants (fixed by the dataset)
#define BB   4
#define HH   8
#define NN   256
#define DVD  64
#define NKD  64
#define EKD  16
#define QD   80      // NK_DIM + EK_DIM
#define TQ   16      // queries per block
#define KC   64      // nk keys per smem chunk
#define NKPAD 68     // padded row stride (floats) for conflict-free LDS

// ============================================================
// Kernel A: E[bh,q,k] = qe[bh,q,:] . ek[bh,q,k,:]
// Pure DRAM stream of ek (134 MB). One block per (bh,q) row,
// one thread per key. Written into the attn region of d_out
// (scratch; kernel B reads it then overwrites with probs).
// ============================================================
__global__ __launch_bounds__(256, 8)
void edge_kernel(const float* __restrict__ qg,
                 const float* __restrict__ ek,
                 float* __restrict__ E)
{
    const int bx   = blockIdx.x;        // bh*256 + q
    const int bh   = bx >> 8;
    const int qrow = bx & 255;
    const int k    = threadIdx.x;

    // qe (16 floats) — uniform across the block, broadcast via L1
    const float4* qp = (const float4*)(qg + ((size_t)(bh * NN) + qrow) * QD + NKD);
    const float4 a0 = qp[0], a1 = qp[1], a2 = qp[2], a3 = qp[3];

    const float4* ekr =
        (const float4*)(ek + ((size_t)(bh * NN + qrow) * NN + k) * EKD);
    const float4 e0 = ekr[0], e1 = ekr[1], e2 = ekr[2], e3 = ekr[3];

    float s = e0.x * a0.x + e0.y * a0.y + e0.z * a0.z + e0.w * a0.w
            + e1.x * a1.x + e1.y * a1.y + e1.z * a1.z + e1.w * a1.w
            + e2.x * a2.x + e2.y * a2.y + e2.z * a2.z + e2.w * a2.w
            + e3.x * a3.x + e3.y * a3.y + e3.z * a3.z + e3.w * a3.w;

    E[(size_t)(bh * NN + qrow) * NN + k] = s;
}

// ============================================================
// Kernel B: node part + E + mask -> softmax -> attn + P@V
// grid = 32 (b*h) * 16 (q tiles) = 512 blocks, 256 threads.
// nk staged through smem; phase 3 uses vectorized uniform LDS.
// ============================================================
__global__ __launch_bounds__(256, 5)
void sdpea_kernel(const float* __restrict__ qg,
                  const float* __restrict__ nk,
                  const float* __restrict__ v,
                  const int*   __restrict__ mask,
                  const float* __restrict__ E,   // == attn_out (scratch)
                  float* __restrict__ out,       // [B,H,N,DV]
                  float* __restrict__ attn_out)  // [B,H,N,N]
{
    __shared__ float qsm[TQ][QD];      // q tile (qn||qe)
    __shared__ float Ssm[TQ][NN];      // scores -> probs
    __shared__ float nks[KC][NKPAD];   // nk chunk, padded

    const int bx = blockIdx.x;
    const int bh = bx >> 4;          // 0..31  (b*H + h)
    const int qt = bx & 15;          // 0..15
    const int b  = bh >> 3;
    const int q0 = qt * TQ;
    const int t  = threadIdx.x;      // 0..255

    // ---- load q tile (16 x 80 floats) ----
    for (int i = t; i < TQ * QD; i += 256) {
        int qq = i / QD, d = i % QD;
        qsm[qq][d] = qg[(size_t)((bh * NN) + q0 + qq) * QD + d];
    }

    // ---- phase 1: scores in 4 key-chunks of 64 ----
    // thread = (k_local = t&63, q_group g = t>>6); queries {g, g+4, g+8, g+12}
    const int kl = t & 63;
    const int g  = t >> 6;
    const float* Ebh  = E + (size_t)bh * NN * NN;
    const int*   mb   = mask + (size_t)b * NN * NN;

    for (int c = 0; c < 4; c++) {
        const int kbase = c * KC;
        __syncthreads();   // protect nks from previous chunk's readers

        // coalesced stage: 64 rows x 64 floats, 4 float4 per thread
        {
            const float4* src = (const float4*)(nk + (size_t)(bh * NN + kbase) * NKD);
            #pragma unroll
            for (int it = 0; it < 4; it++) {
                const int idx  = t + it * 256;       // 0..1023
                const int row  = idx >> 4;           // /16
                const int col4 = idx & 15;
                const float4 vv = src[(size_t)row * 16 + col4];
                *(float4*)&nks[row][col4 * 4] = vv;
            }
        }
        __syncthreads();

        const int k = kbase + kl;

        // prefetch E + mask for this thread's 4 (q,k) pairs
        float ev[4]; int m[4];
        #pragma unroll
        for (int j = 0; j < 4; j++) {
            const int qa = q0 + g + 4 * j;
            ev[j] = Ebh[(size_t)qa * NN + k];
            m[j]  = mb[qa * NN + k];
        }

        float acc0 = 0.f, acc1 = 0.f, acc2 = 0.f, acc3 = 0.f;
        #pragma unroll
        for (int i = 0; i < 16; i++) {
            const float4 nv = *(const float4*)&nks[kl][4 * i];
            const float4 q0v = *(const float4*)&qsm[g     ][4 * i];
            const float4 q1v = *(const float4*)&qsm[g +  4][4 * i];
            const float4 q2v = *(const float4*)&qsm[g +  8][4 * i];
            const float4 q3v = *(const float4*)&qsm[g + 12][4 * i];
            acc0 += nv.x * q0v.x + nv.y * q0v.y + nv.z * q0v.z + nv.w * q0v.w;
            acc1 += nv.x * q1v.x + nv.y * q1v.y + nv.z * q1v.z + nv.w * q1v.w;
            acc2 += nv.x * q2v.x + nv.y * q2v.y + nv.z * q2v.z + nv.w * q2v.w;
            acc3 += nv.x * q3v.x + nv.y * q3v.y + nv.z * q3v.z + nv.w * q3v.w;
        }

        float sv;
        sv = (acc0 + ev[0]) * 0.125f; if (m[0] == 0) sv = -1000000000.0f; Ssm[g     ][k] = sv;
        sv = (acc1 + ev[1]) * 0.125f; if (m[1] == 0) sv = -1000000000.0f; Ssm[g +  4][k] = sv;
        sv = (acc2 + ev[2]) * 0.125f; if (m[2] == 0) sv = -1000000000.0f; Ssm[g +  8][k] = sv;
        sv = (acc3 + ev[3]) * 0.125f; if (m[3] == 0) sv = -1000000000.0f; Ssm[g + 12][k] = sv;
    }
    __syncthreads();

    // ---- phase 2: softmax, one warp per row (8 warps, 16 rows) ----
    {
        const int w = t >> 5, lane = t & 31;
        for (int qq = w; qq < TQ; qq += 8) {
            float vals[8];
            float mx = -3.4e38f;
            #pragma unroll
            for (int i = 0; i < 8; i++) {
                vals[i] = Ssm[qq][lane + 32 * i];
                mx = fmaxf(mx, vals[i]);
            }
            #pragma unroll
            for (int o = 16; o > 0; o >>= 1)
                mx = fmaxf(mx, __shfl_xor_sync(0xffffffffu, mx, o));
            float sum = 0.f;
            #pragma unroll
            for (int i = 0; i < 8; i++) {
                vals[i] = __expf(vals[i] - mx);
                sum += vals[i];
            }
            #pragma unroll
            for (int o = 16; o > 0; o >>= 1)
                sum += __shfl_xor_sync(0xffffffffu, sum, o);
            const float inv = 1.f / sum;
            float* arow = attn_out + (size_t)((bh * NN) + q0 + qq) * NN;
            #pragma unroll
            for (int i = 0; i < 8; i++) {
                float p = vals[i] * inv;
                Ssm[qq][lane + 32 * i] = p;
                arow[lane + 32 * i]    = p;
            }
        }
    }
    __syncthreads();

    // ---- phase 3: output = P @ V ; thread owns (d, 4 q-rows) ----
    // k unrolled by 4: one uniform LDS.128 per q-row per 4 keys.
    {
        const int d = t & 63, gg = t >> 6;      // gg in 0..3
        float acc0 = 0.f, acc1 = 0.f, acc2 = 0.f, acc3 = 0.f;
        const float* vb = v + (size_t)bh * NN * DVD + d;
        #pragma unroll 4
        for (int k = 0; k < NN; k += 4) {
            const float v0 = vb[(size_t)(k    ) * DVD];
            const float v1 = vb[(size_t)(k + 1) * DVD];
            const float v2 = vb[(size_t)(k + 2) * DVD];
            const float v3 = vb[(size_t)(k + 3) * DVD];
            const float4 p0 = *(const float4*)&Ssm[gg     ][k];
            const float4 p1 = *(const float4*)&Ssm[gg +  4][k];
            const float4 p2 = *(const float4*)&Ssm[gg +  8][k];
            const float4 p3 = *(const float4*)&Ssm[gg + 12][k];
            acc0 += p0.x * v0 + p0.y * v1 + p0.z * v2 + p0.w * v3;
            acc1 += p1.x * v0 + p1.y * v1 + p1.z * v2 + p1.w * v3;
            acc2 += p2.x * v0 + p2.y * v1 + p2.z * v2 + p2.w * v3;
            acc3 += p3.x * v0 + p3.y * v1 + p3.z * v2 + p3.w * v3;
        }
        float* ob = out + (size_t)((bh * NN) + q0) * DVD + d;
        ob[(size_t)(gg     ) * DVD] = acc0;
        ob[(size_t)(gg +  4) * DVD] = acc1;
        ob[(size_t)(gg +  8) * DVD] = acc2;
        ob[(size_t)(gg + 12) * DVD] = acc3;
    }
}

extern "C" void kernel_launch(void* const* d_in, const int* in_sizes, int n_in,
                              void* d_out, int out_size)
{
    const float* q    = (const float*)d_in[0];
    const float* nk   = (const float*)d_in[1];
    const float* ek   = (const float*)d_in[2];
    const float* v    = (const float*)d_in[3];
    const int*   mask = (const int*)d_in[4];

    float* out      = (float*)d_out;                       // [4,8,256,64]
    float* attn_out = out + (size_t)BB * HH * NN * DVD;    // [4,8,256,256]

    // Kernel A: edge scores into attn region (scratch)
    edge_kernel<<<BB * HH * NN, 256>>>(q, ek, attn_out);

    // Kernel B: node + E -> softmax -> attn + output
    sdpea_kernel<<<BB * HH * (NN / TQ), 256>>>(q, nk, v, mask,
                                               attn_out, out, attn_out);
}

// round 11
// speedup vs baseline: 1.6395x; 1.0320x over previous
#include <cuda_runtime.h>
#include <cuda_bf16.h>

// Problem constants (fixed by the dataset)
#define BB   4
#define HH   8
#define NN   256
#define DVD  64
#define NKD  64
#define EKD  16
#define QD   80      // NK_DIM + EK_DIM
#define TQ   16      // queries per block
#define KC   64      // nk keys per smem chunk
#define NKPAD 68     // padded row stride (floats) for conflict-free LDS

// ---- packed fp32x2 helpers (FFMA2; ptxas never emits these from C++) ----
__device__ __forceinline__ unsigned long long ffma2(unsigned long long a,
                                                    unsigned long long b,
                                                    unsigned long long c) {
    unsigned long long d;
    asm("fma.rn.f32x2 %0, %1, %2, %3;" : "=l"(d) : "l"(a), "l"(b), "l"(c));
    return d;
}
__device__ __forceinline__ unsigned long long pack2(float lo, float hi) {
    unsigned long long r;
    asm("mov.b64 %0, {%1, %2};" : "=l"(r) : "f"(lo), "f"(hi));
    return r;
}
__device__ __forceinline__ float hadd2(unsigned long long a) {
    float lo, hi;
    asm("mov.b64 {%0, %1}, %2;" : "=f"(lo), "=f"(hi) : "l"(a));
    return lo + hi;
}

// ============================================================
// Kernel A: E[bh,q,k] = qe[bh,q,:] . ek[bh,q,k,:]
// Pure DRAM stream of ek (134 MB). One block per (bh,q) row,
// one thread per key. Written into the attn region of d_out
// (scratch; kernel B reads it then overwrites with probs).
// ============================================================
__global__ __launch_bounds__(256, 8)
void edge_kernel(const float* __restrict__ qg,
                 const float* __restrict__ ek,
                 float* __restrict__ E)
{
    const int bx   = blockIdx.x;        // bh*256 + q
    const int bh   = bx >> 8;
    const int qrow = bx & 255;
    const int k    = threadIdx.x;

    // qe (16 floats) — uniform across the block, broadcast via L1
    const float4* qp = (const float4*)(qg + ((size_t)(bh * NN) + qrow) * QD + NKD);
    const float4 a0 = qp[0], a1 = qp[1], a2 = qp[2], a3 = qp[3];

    const float4* ekr =
        (const float4*)(ek + ((size_t)(bh * NN + qrow) * NN + k) * EKD);
    const float4 e0 = ekr[0], e1 = ekr[1], e2 = ekr[2], e3 = ekr[3];

    float s = e0.x * a0.x + e0.y * a0.y + e0.z * a0.z + e0.w * a0.w
            + e1.x * a1.x + e1.y * a1.y + e1.z * a1.z + e1.w * a1.w
            + e2.x * a2.x + e2.y * a2.y + e2.z * a2.z + e2.w * a2.w
            + e3.x * a3.x + e3.y * a3.y + e3.z * a3.z + e3.w * a3.w;

    E[(size_t)(bh * NN + qrow) * NN + k] = s;
}

// ============================================================
// Kernel B: node part + E + mask -> softmax -> attn + P@V
// grid = 32 (b*h) * 16 (q tiles) = 512 blocks, 256 threads.
// nk staged through smem; FFMA2-packed dot products.
// ============================================================
__global__ __launch_bounds__(256, 5)
void sdpea_kernel(const float* __restrict__ qg,
                  const float* __restrict__ nk,
                  const float* __restrict__ v,
                  const int*   __restrict__ mask,
                  const float* __restrict__ E,   // == attn_out (scratch)
                  float* __restrict__ out,       // [B,H,N,DV]
                  float* __restrict__ attn_out)  // [B,H,N,N]
{
    __shared__ float qsm[TQ][QD];      // q tile (qn||qe), rows 320B (16B aligned)
    __shared__ float Ssm[TQ][NN];      // scores -> probs
    __shared__ float nks[KC][NKPAD];   // nk chunk, padded (rows 272B, 16B aligned)

    const int bx = blockIdx.x;
    const int bh = bx >> 4;          // 0..31  (b*H + h)
    const int qt = bx & 15;          // 0..15
    const int b  = bh >> 3;
    const int q0 = qt * TQ;
    const int t  = threadIdx.x;      // 0..255

    // ---- load q tile (16 x 80 floats) ----
    for (int i = t; i < TQ * QD; i += 256) {
        int qq = i / QD, d = i % QD;
        qsm[qq][d] = qg[(size_t)((bh * NN) + q0 + qq) * QD + d];
    }

    // ---- phase 1: scores in 4 key-chunks of 64 ----
    // thread = (k_local = t&63, q_group g = t>>6); queries {g, g+4, g+8, g+12}
    const int kl = t & 63;
    const int g  = t >> 6;
    const float* Ebh  = E + (size_t)bh * NN * NN;
    const int*   mb   = mask + (size_t)b * NN * NN;

    for (int c = 0; c < 4; c++) {
        const int kbase = c * KC;
        __syncthreads();   // protect nks from previous chunk's readers

        // coalesced stage: 64 rows x 64 floats, 4 float4 per thread
        {
            const float4* src = (const float4*)(nk + (size_t)(bh * NN + kbase) * NKD);
            #pragma unroll
            for (int it = 0; it < 4; it++) {
                const int idx  = t + it * 256;       // 0..1023
                const int row  = idx >> 4;           // /16
                const int col4 = idx & 15;
                const float4 vv = src[(size_t)row * 16 + col4];
                *(float4*)&nks[row][col4 * 4] = vv;
            }
        }
        __syncthreads();

        const int k = kbase + kl;

        // prefetch E + mask for this thread's 4 (q,k) pairs
        float ev[4]; int m[4];
        #pragma unroll
        for (int j = 0; j < 4; j++) {
            const int qa = q0 + g + 4 * j;
            ev[j] = Ebh[(size_t)qa * NN + k];
            m[j]  = mb[qa * NN + k];
        }

        // packed dot products: acc[q] is an f32x2 pair, halves summed at end
        unsigned long long acc0 = 0ull, acc1 = 0ull, acc2 = 0ull, acc3 = 0ull;
        #pragma unroll
        for (int i = 0; i < 16; i++) {
            const ulonglong2 nv  = *(const ulonglong2*)&nks[kl][4 * i];
            const ulonglong2 q0v = *(const ulonglong2*)&qsm[g     ][4 * i];
            const ulonglong2 q1v = *(const ulonglong2*)&qsm[g +  4][4 * i];
            const ulonglong2 q2v = *(const ulonglong2*)&qsm[g +  8][4 * i];
            const ulonglong2 q3v = *(const ulonglong2*)&qsm[g + 12][4 * i];
            acc0 = ffma2(nv.x, q0v.x, acc0); acc0 = ffma2(nv.y, q0v.y, acc0);
            acc1 = ffma2(nv.x, q1v.x, acc1); acc1 = ffma2(nv.y, q1v.y, acc1);
            acc2 = ffma2(nv.x, q2v.x, acc2); acc2 = ffma2(nv.y, q2v.y, acc2);
            acc3 = ffma2(nv.x, q3v.x, acc3); acc3 = ffma2(nv.y, q3v.y, acc3);
        }

        float sv;
        sv = (hadd2(acc0) + ev[0]) * 0.125f; if (m[0] == 0) sv = -1000000000.0f; Ssm[g     ][k] = sv;
        sv = (hadd2(acc1) + ev[1]) * 0.125f; if (m[1] == 0) sv = -1000000000.0f; Ssm[g +  4][k] = sv;
        sv = (hadd2(acc2) + ev[2]) * 0.125f; if (m[2] == 0) sv = -1000000000.0f; Ssm[g +  8][k] = sv;
        sv = (hadd2(acc3) + ev[3]) * 0.125f; if (m[3] == 0) sv = -1000000000.0f; Ssm[g + 12][k] = sv;
    }
    __syncthreads();

    // ---- phase 2: softmax, one warp per row (8 warps, 16 rows) ----
    {
        const int w = t >> 5, lane = t & 31;
        for (int qq = w; qq < TQ; qq += 8) {
            float vals[8];
            float mx = -3.4e38f;
            #pragma unroll
            for (int i = 0; i < 8; i++) {
                vals[i] = Ssm[qq][lane + 32 * i];
                mx = fmaxf(mx, vals[i]);
            }
            #pragma unroll
            for (int o = 16; o > 0; o >>= 1)
                mx = fmaxf(mx, __shfl_xor_sync(0xffffffffu, mx, o));
            float sum = 0.f;
            #pragma unroll
            for (int i = 0; i < 8; i++) {
                vals[i] = __expf(vals[i] - mx);
                sum += vals[i];
            }
            #pragma unroll
            for (int o = 16; o > 0; o >>= 1)
                sum += __shfl_xor_sync(0xffffffffu, sum, o);
            const float inv = 1.f / sum;
            float* arow = attn_out + (size_t)((bh * NN) + q0 + qq) * NN;
            #pragma unroll
            for (int i = 0; i < 8; i++) {
                float p = vals[i] * inv;
                Ssm[qq][lane + 32 * i] = p;
                arow[lane + 32 * i]    = p;
            }
        }
    }
    __syncthreads();

    // ---- phase 3: output = P @ V ; thread owns (d, 4 q-rows) ----
    // k unrolled by 4: uniform LDS.128 probs (pre-packed pairs) + packed FMAs.
    {
        const int d = t & 63, gg = t >> 6;      // gg in 0..3
        unsigned long long acc0 = 0ull, acc1 = 0ull, acc2 = 0ull, acc3 = 0ull;
        const float* vb = v + (size_t)bh * NN * DVD + d;
        #pragma unroll 4
        for (int k = 0; k < NN; k += 4) {
            const float v0 = vb[(size_t)(k    ) * DVD];
            const float v1 = vb[(size_t)(k + 1) * DVD];
            const float v2 = vb[(size_t)(k + 2) * DVD];
            const float v3 = vb[(size_t)(k + 3) * DVD];
            const unsigned long long vp01 = pack2(v0, v1);
            const unsigned long long vp23 = pack2(v2, v3);
            const ulonglong2 p0 = *(const ulonglong2*)&Ssm[gg     ][k];
            const ulonglong2 p1 = *(const ulonglong2*)&Ssm[gg +  4][k];
            const ulonglong2 p2 = *(const ulonglong2*)&Ssm[gg +  8][k];
            const ulonglong2 p3 = *(const ulonglong2*)&Ssm[gg + 12][k];
            acc0 = ffma2(p0.x, vp01, acc0); acc0 = ffma2(p0.y, vp23, acc0);
            acc1 = ffma2(p1.x, vp01, acc1); acc1 = ffma2(p1.y, vp23, acc1);
            acc2 = ffma2(p2.x, vp01, acc2); acc2 = ffma2(p2.y, vp23, acc2);
            acc3 = ffma2(p3.x, vp01, acc3); acc3 = ffma2(p3.y, vp23, acc3);
        }
        float* ob = out + (size_t)((bh * NN) + q0) * DVD + d;
        ob[(size_t)(gg     ) * DVD] = hadd2(acc0);
        ob[(size_t)(gg +  4) * DVD] = hadd2(acc1);
        ob[(size_t)(gg +  8) * DVD] = hadd2(acc2);
        ob[(size_t)(gg + 12) * DVD] = hadd2(acc3);
    }
}

extern "C" void kernel_launch(void* const* d_in, const int* in_sizes, int n_in,
                              void* d_out, int out_size)
{
    const float* q    = (const float*)d_in[0];
    const float* nk   = (const float*)d_in[1];
    const float* ek   = (const float*)d_in[2];
    const float* v    = (const float*)d_in[3];
    const int*   mask = (const int*)d_in[4];

    float* out      = (float*)d_out;                       // [4,8,256,64]
    float* attn_out = out + (size_t)BB * HH * NN * DVD;    // [4,8,256,256]

    // Kernel A: edge scores into attn region (scratch)
    edge_kernel<<<BB * HH * NN, 256>>>(q, ek, attn_out);

    // Kernel B: node + E -> softmax -> attn + output
    sdpea_kernel<<<BB * HH * (NN / TQ), 256>>>(q, nk, v, mask,
                                               attn_out, out, attn_out);
}

// round 12
// speedup vs baseline: 1.6511x; 1.0070x over previous
#include <cuda_runtime.h>
#include <cuda_bf16.h>

// Problem constants (fixed by the dataset)
#define BB   4
#define HH   8
#define NN   256
#define DVD  64
#define NKD  64
#define EKD  16
#define QD   80      // NK_DIM + EK_DIM
#define TQ   16      // queries per block
#define KC   64      // nk keys per smem chunk
#define NKPAD 68     // padded row stride (floats) for conflict-free LDS

// ---- packed fp32x2 helpers (FFMA2; ptxas never emits these from C++) ----
__device__ __forceinline__ unsigned long long ffma2(unsigned long long a,
                                                    unsigned long long b,
                                                    unsigned long long c) {
    unsigned long long d;
    asm("fma.rn.f32x2 %0, %1, %2, %3;" : "=l"(d) : "l"(a), "l"(b), "l"(c));
    return d;
}
__device__ __forceinline__ unsigned long long pack2(float lo, float hi) {
    unsigned long long r;
    asm("mov.b64 %0, {%1, %2};" : "=l"(r) : "f"(lo), "f"(hi));
    return r;
}
__device__ __forceinline__ float hadd2(unsigned long long a) {
    float lo, hi;
    asm("mov.b64 {%0, %1}, %2;" : "=f"(lo), "=f"(hi) : "l"(a));
    return lo + hi;
}

// ============================================================
// Fused kernel: (node + edge) scores -> softmax -> attn + P@V
// grid = 32 (b*h) * 16 (q tiles) = 512 blocks, 256 threads.
// nk staged through smem; ek streamed straight from DRAM with
// coalesced double-buffered LDG.128; FFMA2-packed dot products.
// ============================================================
__global__ __launch_bounds__(256, 4)
void sdpea_kernel(const float* __restrict__ qg,
                  const float* __restrict__ nk,
                  const float* __restrict__ ek,
                  const float* __restrict__ v,
                  const int*   __restrict__ mask,
                  float* __restrict__ out,       // [B,H,N,DV]
                  float* __restrict__ attn_out)  // [B,H,N,N]
{
    __shared__ float qsm[TQ][QD];      // q tile (qn||qe), rows 320B (16B aligned)
    __shared__ float Ssm[TQ][NN];      // scores -> probs
    __shared__ float nks[KC][NKPAD];   // nk chunk, padded

    const int bx = blockIdx.x;
    const int bh = bx >> 4;          // 0..31  (b*H + h)
    const int qt = bx & 15;          // 0..15
    const int b  = bh >> 3;
    const int q0 = qt * TQ;
    const int t  = threadIdx.x;      // 0..255

    // ---- load q tile (16 x 80 floats) ----
    for (int i = t; i < TQ * QD; i += 256) {
        int qq = i / QD, d = i % QD;
        qsm[qq][d] = qg[(size_t)((bh * NN) + q0 + qq) * QD + d];
    }

    // ---- phase 1: scores in 4 key-chunks of 64 ----
    // thread = (k_local = t&63, q_group g = t>>6); queries {g, g+4, g+8, g+12}
    const int kl = t & 63;
    const int g  = t >> 6;
    const int*   mb  = mask + (size_t)b * NN * NN;
    const float* ekb = ek + (size_t)bh * NN * NN * EKD;   // [q][k][16]

    for (int c = 0; c < 4; c++) {
        const int kbase = c * KC;
        __syncthreads();   // protect nks from previous chunk's readers

        // coalesced stage: 64 rows x 64 floats, 4 float4 per thread
        {
            const float4* src = (const float4*)(nk + (size_t)(bh * NN + kbase) * NKD);
            #pragma unroll
            for (int it = 0; it < 4; it++) {
                const int idx  = t + it * 256;       // 0..1023
                const int row  = idx >> 4;           // /16
                const int col4 = idx & 15;
                const float4 vv = src[(size_t)row * 16 + col4];
                *(float4*)&nks[row][col4 * 4] = vv;
            }
        }
        __syncthreads();

        const int k = kbase + kl;

        // mask prefetch for this thread's 4 (q,k) pairs
        int m[4];
        #pragma unroll
        for (int j = 0; j < 4; j++)
            m[j] = mb[(q0 + g + 4 * j) * NN + k];

        // ---- edge part: stream ek rows, double-buffered LDG.128 ----
        // acc[q] are packed f32x2 accumulators shared by edge + node parts.
        unsigned long long acc[4] = {0ull, 0ull, 0ull, 0ull};
        float4 ebuf[2][4];
        {
            const float4* er0 =
                (const float4*)(ekb + ((size_t)(q0 + g) * NN + k) * EKD);
            #pragma unroll
            for (int i = 0; i < 4; i++) ebuf[0][i] = er0[i];
        }
        #pragma unroll
        for (int j = 0; j < 4; j++) {
            if (j < 3) {
                const float4* ern =
                    (const float4*)(ekb + ((size_t)(q0 + g + 4 * (j + 1)) * NN + k) * EKD);
                #pragma unroll
                for (int i = 0; i < 4; i++) ebuf[(j + 1) & 1][i] = ern[i];
            }
            const float4* e = ebuf[j & 1];
            const ulonglong2* qe =
                (const ulonglong2*)&qsm[g + 4 * j][NKD];
            #pragma unroll
            for (int i = 0; i < 4; i++) {
                const unsigned long long elo = pack2(e[i].x, e[i].y);
                const unsigned long long ehi = pack2(e[i].z, e[i].w);
                acc[j] = ffma2(elo, qe[i].x, acc[j]);
                acc[j] = ffma2(ehi, qe[i].y, acc[j]);
            }
        }

        // ---- node part: smem nk chunk x q tile ----
        unsigned long long a0 = acc[0], a1 = acc[1], a2 = acc[2], a3 = acc[3];
        #pragma unroll
        for (int i = 0; i < 16; i++) {
            const ulonglong2 nv  = *(const ulonglong2*)&nks[kl][4 * i];
            const ulonglong2 q0v = *(const ulonglong2*)&qsm[g     ][4 * i];
            const ulonglong2 q1v = *(const ulonglong2*)&qsm[g +  4][4 * i];
            const ulonglong2 q2v = *(const ulonglong2*)&qsm[g +  8][4 * i];
            const ulonglong2 q3v = *(const ulonglong2*)&qsm[g + 12][4 * i];
            a0 = ffma2(nv.x, q0v.x, a0); a0 = ffma2(nv.y, q0v.y, a0);
            a1 = ffma2(nv.x, q1v.x, a1); a1 = ffma2(nv.y, q1v.y, a1);
            a2 = ffma2(nv.x, q2v.x, a2); a2 = ffma2(nv.y, q2v.y, a2);
            a3 = ffma2(nv.x, q3v.x, a3); a3 = ffma2(nv.y, q3v.y, a3);
        }

        float sv;
        sv = hadd2(a0) * 0.125f; if (m[0] == 0) sv = -1000000000.0f; Ssm[g     ][k] = sv;
        sv = hadd2(a1) * 0.125f; if (m[1] == 0) sv = -1000000000.0f; Ssm[g +  4][k] = sv;
        sv = hadd2(a2) * 0.125f; if (m[2] == 0) sv = -1000000000.0f; Ssm[g +  8][k] = sv;
        sv = hadd2(a3) * 0.125f; if (m[3] == 0) sv = -1000000000.0f; Ssm[g + 12][k] = sv;
    }
    __syncthreads();

    // ---- phase 2: softmax, one warp per row (8 warps, 16 rows) ----
    {
        const int w = t >> 5, lane = t & 31;
        for (int qq = w; qq < TQ; qq += 8) {
            float vals[8];
            float mx = -3.4e38f;
            #pragma unroll
            for (int i = 0; i < 8; i++) {
                vals[i] = Ssm[qq][lane + 32 * i];
                mx = fmaxf(mx, vals[i]);
            }
            #pragma unroll
            for (int o = 16; o > 0; o >>= 1)
                mx = fmaxf(mx, __shfl_xor_sync(0xffffffffu, mx, o));
            float sum = 0.f;
            #pragma unroll
            for (int i = 0; i < 8; i++) {
                vals[i] = __expf(vals[i] - mx);
                sum += vals[i];
            }
            #pragma unroll
            for (int o = 16; o > 0; o >>= 1)
                sum += __shfl_xor_sync(0xffffffffu, sum, o);
            const float inv = 1.f / sum;
            float* arow = attn_out + (size_t)((bh * NN) + q0 + qq) * NN;
            #pragma unroll
            for (int i = 0; i < 8; i++) {
                float p = vals[i] * inv;
                Ssm[qq][lane + 32 * i] = p;
                arow[lane + 32 * i]    = p;
            }
        }
    }
    __syncthreads();

    // ---- phase 3: output = P @ V ; thread owns (d, 4 q-rows) ----
    // k unrolled by 4: uniform LDS.128 probs (pre-packed pairs) + packed FMAs.
    {
        const int d = t & 63, gg = t >> 6;      // gg in 0..3
        unsigned long long acc0 = 0ull, acc1 = 0ull, acc2 = 0ull, acc3 = 0ull;
        const float* vb = v + (size_t)bh * NN * DVD + d;
        #pragma unroll 4
        for (int k = 0; k < NN; k += 4) {
            const float v0 = vb[(size_t)(k    ) * DVD];
            const float v1 = vb[(size_t)(k + 1) * DVD];
            const float v2 = vb[(size_t)(k + 2) * DVD];
            const float v3 = vb[(size_t)(k + 3) * DVD];
            const unsigned long long vp01 = pack2(v0, v1);
            const unsigned long long vp23 = pack2(v2, v3);
            const ulonglong2 p0 = *(const ulonglong2*)&Ssm[gg     ][k];
            const ulonglong2 p1 = *(const ulonglong2*)&Ssm[gg +  4][k];
            const ulonglong2 p2 = *(const ulonglong2*)&Ssm[gg +  8][k];
            const ulonglong2 p3 = *(const ulonglong2*)&Ssm[gg + 12][k];
            acc0 = ffma2(p0.x, vp01, acc0); acc0 = ffma2(p0.y, vp23, acc0);
            acc1 = ffma2(p1.x, vp01, acc1); acc1 = ffma2(p1.y, vp23, acc1);
            acc2 = ffma2(p2.x, vp01, acc2); acc2 = ffma2(p2.y, vp23, acc2);
            acc3 = ffma2(p3.x, vp01, acc3); acc3 = ffma2(p3.y, vp23, acc3);
        }
        float* ob = out + (size_t)((bh * NN) + q0) * DVD + d;
        ob[(size_t)(gg     ) * DVD] = hadd2(acc0);
        ob[(size_t)(gg +  4) * DVD] = hadd2(acc1);
        ob[(size_t)(gg +  8) * DVD] = hadd2(acc2);
        ob[(size_t)(gg + 12) * DVD] = hadd2(acc3);
    }
}

extern "C" void kernel_launch(void* const* d_in, const int* in_sizes, int n_in,
                              void* d_out, int out_size)
{
    const float* q    = (const float*)d_in[0];
    const float* nk   = (const float*)d_in[1];
    const float* ek   = (const float*)d_in[2];
    const float* v    = (const float*)d_in[3];
    const int*   mask = (const int*)d_in[4];

    float* out      = (float*)d_out;                       // [4,8,256,64]
    float* attn_out = out + (size_t)BB * HH * NN * DVD;    // [4,8,256,256]

    sdpea_kernel<<<BB * HH * (NN / TQ), 256>>>(q, nk, ek, v, mask,
                                               out, attn_out);
}